// round 14
// baseline (speedup 1.0000x reference)
#include <cuda_runtime.h>
#include <cuda_fp16.h>

#define N_NODES 50000
#define N_EDGES 800000
#define D 64
#define GRID 592                         // 148 SMs x 4 blocks/SM
#define TPB 256
#define NCSR 250                         // blocks 0..249: CSR build; rest: proj0 overlap
#define CH 200                           // 250*200 = 50000 exact
#define TILE 32
#define NT ((N_NODES + TILE - 1) / TILE) // 1563 proj tiles
#define NWT4 (N_NODES / 4)               // 12500 agg warp-tiles of 4 rows
#define A_ST 72                          // A smem stride (halves)
#define W_ST 136                         // W smem stride (halves)

typedef unsigned long long ull;
typedef unsigned int u32;

// ---------------- scratch (static device globals; no allocation) ----------------
__device__ int   g_degcnt[N_NODES];
__device__ int   g_cursor[N_NODES];
__device__ int   g_rs[N_NODES + 1];
__device__ int   g_csr[N_EDGES];
__device__ int   g_bsum[NCSR];
__device__ int   g_boff[NCSR];
__device__ int   g_tile[4];              // proj0, agg0, proj1, agg1
__device__ float g_h[N_NODES * D];       // S then hidden h
__device__ u32   g_ph[N_NODES * (D / 2)];// P as half2

// barrier state: monotonic (replay-safe). id 0: global; id 1: CSR partial
__device__ unsigned g_bc[2];
__device__ unsigned g_bg[2];

__device__ __forceinline__ void bar_n(int id, unsigned nblk) {
    __syncthreads();
    if (threadIdx.x == 0) {
        __threadfence();
        unsigned my = atomicAdd(&g_bc[id], 1u) + 1u;
        unsigned need = (my + nblk - 1u) / nblk;
        if ((my % nblk) == 0u) atomicAdd(&g_bg[id], 1u);
        while (*(volatile unsigned*)&g_bg[id] < need) {}
        __threadfence();
    }
    __syncthreads();
}

__device__ __forceinline__ int load_idx(const void* p, int e, bool is64) {
    return is64 ? (int)((const long long*)p)[e] : ((const int*)p)[e];
}

// ---------------- mma helpers ----------------
__device__ __forceinline__ void ldsm_x4(u32& r0, u32& r1, u32& r2, u32& r3, u32 addr) {
    asm volatile("ldmatrix.sync.aligned.m8n8.x4.shared.b16 {%0,%1,%2,%3}, [%4];"
                 : "=r"(r0), "=r"(r1), "=r"(r2), "=r"(r3) : "r"(addr));
}
__device__ __forceinline__ void ldsm_x2_t(u32& r0, u32& r1, u32 addr) {
    asm volatile("ldmatrix.sync.aligned.m8n8.x2.trans.shared.b16 {%0,%1}, [%2];"
                 : "=r"(r0), "=r"(r1) : "r"(addr));
}
__device__ __forceinline__ void mma16816(float* c, const u32* a, u32 b0, u32 b1) {
    asm volatile(
        "mma.sync.aligned.m16n8k16.row.col.f32.f16.f16.f32 "
        "{%0,%1,%2,%3}, {%4,%5,%6,%7}, {%8,%9}, {%0,%1,%2,%3};"
        : "+f"(c[0]), "+f"(c[1]), "+f"(c[2]), "+f"(c[3])
        : "r"(a[0]), "r"(a[1]), "r"(a[2]), "r"(a[3]), "r"(b0), "r"(b1));
}

// ---------------- shared memory ----------------
__shared__ __align__(16) __half Ah[TILE * A_ST];   // 4.6 KB
__shared__ __align__(16) __half Wh[D * W_ST];      // 17.4 KB  [k][n: Ws|Wn] fp16
__shared__ int sscan[TPB];

// ---------------- W staging (once per proj phase) ----------------
__device__ __forceinline__ void stage_W(const float* __restrict__ Ws,
                                        const float* __restrict__ Wn, int tid) {
    for (int idx = tid; idx < D * 128; idx += TPB) {
        int k = idx >> 7, n = idx & 127;
        float w = (n < D) ? Ws[k * D + n] : Wn[k * D + (n - D)];
        Wh[k * W_ST + n] = __float2half(w);
    }
}

// ---------------- dense projection via HMMA: S = inp@Ws (fp32), P = inp@Wn (fp16) ----------------
__device__ void dense_proj(const float* __restrict__ inp, float* __restrict__ outS,
                           int ctr, int tid) {
    const int lane = tid & 31;
    const int w = tid >> 5;
    const int mg = w & 1;                // 16-row group
    const int nq = w >> 1;               // 32-col group: 0,1 -> S ; 2,3 -> P
    const int gid = lane >> 2;
    const int tig = lane & 3;
    __shared__ int s_t;

    const u32 ah_base = (u32)__cvta_generic_to_shared(Ah);
    const u32 wh_base = (u32)__cvta_generic_to_shared(Wh);
    const u32 a_lane = ah_base + ((mg * 16 + (lane & 15)) * A_ST + (lane >> 4) * 8) * 2;
    const u32 b_lane = wh_base + ((lane & 15) * W_ST + nq * 32) * 2;

    for (;;) {
        __syncthreads();
        if (tid == 0) s_t = atomicAdd(&g_tile[ctr], 1);
        __syncthreads();
        const int t = s_t;
        if (t >= NT) break;
        const int row0 = t * TILE;

        // stage A tile (32 x 64 fp16)
        {
            int r = tid >> 3, c = (tid & 7) * 8;
            int gr = row0 + r;
            float4 v0 = make_float4(0.f, 0.f, 0.f, 0.f), v1 = v0;
            if (gr < N_NODES) {
                v0 = *(const float4*)(inp + (long long)gr * D + c);
                v1 = *(const float4*)(inp + (long long)gr * D + c + 4);
            }
            __half2 h0 = __float22half2_rn(make_float2(v0.x, v0.y));
            __half2 h1 = __float22half2_rn(make_float2(v0.z, v0.w));
            __half2 h2 = __float22half2_rn(make_float2(v1.x, v1.y));
            __half2 h3 = __float22half2_rn(make_float2(v1.z, v1.w));
            uint4 pk;
            pk.x = *(u32*)&h0; pk.y = *(u32*)&h1; pk.z = *(u32*)&h2; pk.w = *(u32*)&h3;
            *(uint4*)&Ah[r * A_ST + c] = pk;
        }
        __syncthreads();

        float acc[4][4];
#pragma unroll
        for (int i = 0; i < 4; i++)
#pragma unroll
            for (int j = 0; j < 4; j++) acc[i][j] = 0.f;

#pragma unroll
        for (int kb = 0; kb < 4; kb++) {
            u32 a0, a1, a2, a3;
            ldsm_x4(a0, a1, a2, a3, a_lane + kb * 32);
            u32 af[4] = {a0, a1, a2, a3};
#pragma unroll
            for (int nb = 0; nb < 4; nb++) {
                u32 b0, b1;
                ldsm_x2_t(b0, b1, b_lane + (kb * 16 * W_ST + nb * 8) * 2);
                mma16816(acc[nb], af, b0, b1);
            }
        }

        const int r0g = row0 + mg * 16 + gid;
        const int r1g = r0g + 8;
        if (nq < 2) {
#pragma unroll
            for (int nb = 0; nb < 4; nb++) {
                int col = nq * 32 + nb * 8 + tig * 2;
                if (r0g < N_NODES)
                    *(float2*)(outS + (long long)r0g * D + col) = make_float2(acc[nb][0], acc[nb][1]);
                if (r1g < N_NODES)
                    *(float2*)(outS + (long long)r1g * D + col) = make_float2(acc[nb][2], acc[nb][3]);
            }
        } else {
#pragma unroll
            for (int nb = 0; nb < 4; nb++) {
                int col = (nq - 2) * 32 + nb * 8 + tig * 2;
                if (r0g < N_NODES) {
                    __half2 h = __float22half2_rn(make_float2(acc[nb][0], acc[nb][1]));
                    g_ph[r0g * (D / 2) + (col >> 1)] = *(u32*)&h;
                }
                if (r1g < N_NODES) {
                    __half2 h = __float22half2_rn(make_float2(acc[nb][2], acc[nb][3]));
                    g_ph[r1g * (D / 2) + (col >> 1)] = *(u32*)&h;
                }
            }
        }
    }
}

// ---------------- aggregation (software-pipelined gather) ----------------
template <bool RELU>
__device__ void agg_combine(float* __restrict__ io, const float* __restrict__ bias,
                            int ctr, int tid) {
    const int lane = tid & 31;
    const int q = lane >> 3;
    const int lq = lane & 7;
    float4 bv0 = *(const float4*)(bias + 8 * lq);
    float4 bv1 = *(const float4*)(bias + 8 * lq + 4);

    for (;;) {
        int t = 0;
        if (lane == 0) t = atomicAdd(&g_tile[ctr], 1);
        t = __shfl_sync(0xffffffffu, t, 0);
        if (t >= NWT4) break;
        const int row0 = t * 4;

        int rsv = 0;
        if (lane < 5) rsv = g_rs[row0 + lane];
        const int beg = __shfl_sync(0xffffffffu, rsv, q);
        const int end = __shfl_sync(0xffffffffu, rsv, q + 1);
        const int gr = row0 + q;
        const float iv = 1.0f / fmaxf((float)(end - beg), 1.0f);

        float2 ac0 = make_float2(0.f, 0.f), ac1 = ac0, ac2 = ac0, ac3 = ac0;
#define ACC8(U)                                                                        \
        {                                                                              \
            float2 f;                                                                  \
            f = __half22float2(*(__half2*)&(U).x); ac0.x += f.x; ac0.y += f.y;         \
            f = __half22float2(*(__half2*)&(U).y); ac1.x += f.x; ac1.y += f.y;         \
            f = __half22float2(*(__half2*)&(U).z); ac2.x += f.x; ac2.y += f.y;         \
            f = __half22float2(*(__half2*)&(U).w); ac3.x += f.x; ac3.y += f.y;         \
        }
        const int n4 = (end - beg) >> 2;      // full 4-edge batches
        int e = beg;
        if (n4 > 0) {
            // prologue: load first index batch
            int s0 = g_csr[e], s1 = g_csr[e + 1], s2 = g_csr[e + 2], s3 = g_csr[e + 3];
            for (int it = 0; it < n4; it++) {
                // issue feature loads for current batch
                uint4 u0 = __ldg((const uint4*)(g_ph + s0 * (D / 2)) + lq);
                uint4 u1 = __ldg((const uint4*)(g_ph + s1 * (D / 2)) + lq);
                uint4 u2 = __ldg((const uint4*)(g_ph + s2 * (D / 2)) + lq);
                uint4 u3 = __ldg((const uint4*)(g_ph + s3 * (D / 2)) + lq);
                e += 4;
                // prefetch next batch's indices while features are in flight
                if (it + 1 < n4) {
                    s0 = g_csr[e]; s1 = g_csr[e + 1];
                    s2 = g_csr[e + 2]; s3 = g_csr[e + 3];
                }
                ACC8(u0) ACC8(u1) ACC8(u2) ACC8(u3)
            }
        }
        for (; e < end; e++) {
            int s0 = g_csr[e];
            uint4 u0 = __ldg((const uint4*)(g_ph + s0 * (D / 2)) + lq);
            ACC8(u0)
        }
#undef ACC8
        float4 s0v = *((const float4*)(io + (long long)gr * D + 8 * lq));
        float4 s1v = *((const float4*)(io + (long long)gr * D + 8 * lq + 4));
        float4 o0, o1;
        o0.x = s0v.x + ac0.x * iv + bv0.x;
        o0.y = s0v.y + ac0.y * iv + bv0.y;
        o0.z = s0v.z + ac1.x * iv + bv0.z;
        o0.w = s0v.w + ac1.y * iv + bv0.w;
        o1.x = s1v.x + ac2.x * iv + bv1.x;
        o1.y = s1v.y + ac2.y * iv + bv1.y;
        o1.z = s1v.z + ac3.x * iv + bv1.z;
        o1.w = s1v.w + ac3.y * iv + bv1.w;
        if (RELU) {
            o0.x = fmaxf(o0.x, 0.f); o0.y = fmaxf(o0.y, 0.f);
            o0.z = fmaxf(o0.z, 0.f); o0.w = fmaxf(o0.w, 0.f);
            o1.x = fmaxf(o1.x, 0.f); o1.y = fmaxf(o1.y, 0.f);
            o1.z = fmaxf(o1.z, 0.f); o1.w = fmaxf(o1.w, 0.f);
        }
        *((float4*)(io + (long long)gr * D + 8 * lq)) = o0;
        *((float4*)(io + (long long)gr * D + 8 * lq + 4)) = o1;
    }
}

// ---------------- fused persistent kernel ----------------
__global__ void __launch_bounds__(TPB, 4)
sage_fused_kernel(const float* __restrict__ x,
                  const void* __restrict__ srcp,
                  const void* __restrict__ dstp,
                  const float* __restrict__ W_self0, const float* __restrict__ W_neigh0,
                  const float* __restrict__ b0,
                  const float* __restrict__ W_self1, const float* __restrict__ W_neigh1,
                  const float* __restrict__ b1,
                  float* __restrict__ outp) {
    const int tid = threadIdx.x;
    const int bid = blockIdx.x;

    // ---- index dtype detection ----
    if (tid == 0) sscan[0] = 0;
    __syncthreads();
    {
        int any = 0;
        const int* si = (const int*)srcp;
        for (int i = tid; i < 2048; i += TPB) any |= si[2 * i + 1];
        if (any) atomicOr(&sscan[0], 1);
    }
    __syncthreads();
    const bool is64 = (sscan[0] == 0);

    if (bid < NCSR) {
        // ================= CSR-builder role =================
        const int gt = bid * TPB + tid;
        const int gs = NCSR * TPB;
        for (int j = gt; j < N_NODES; j += gs) { g_degcnt[j] = 0; g_cursor[j] = 0; }
        if (gt >= 1 && gt < 4) g_tile[gt] = 0;
        bar_n(1, NCSR);
        for (int e = gt; e < N_EDGES; e += gs)
            atomicAdd(&g_degcnt[load_idx(dstp, e, is64)], 1);
        bar_n(1, NCSR);
        {
            int n0 = bid * CH;
            int v = (tid < CH) ? g_degcnt[n0 + tid] : 0;
            sscan[tid] = v; __syncthreads();
            for (int off = TPB / 2; off > 0; off >>= 1) {
                if (tid < off) sscan[tid] += sscan[tid + off];
                __syncthreads();
            }
            if (tid == 0) g_bsum[bid] = sscan[0];
        }
        bar_n(1, NCSR);
        if (bid == 0) {
            int v = (tid < NCSR) ? g_bsum[tid] : 0;
            sscan[tid] = v; __syncthreads();
            for (int off = 1; off < TPB; off <<= 1) {
                int t2 = (tid >= off) ? sscan[tid - off] : 0;
                __syncthreads();
                sscan[tid] += t2;
                __syncthreads();
            }
            if (tid < NCSR) g_boff[tid] = sscan[tid] - v;
        }
        bar_n(1, NCSR);
        {
            int n0 = bid * CH;
            int v = (tid < CH) ? g_degcnt[n0 + tid] : 0;
            sscan[tid] = v; __syncthreads();
            for (int off = 1; off < TPB; off <<= 1) {
                int t2 = (tid >= off) ? sscan[tid - off] : 0;
                __syncthreads();
                sscan[tid] += t2;
                __syncthreads();
            }
            if (tid < CH) g_rs[n0 + tid] = g_boff[bid] + sscan[tid] - v;
            if (bid == 0 && tid == 0) g_rs[N_NODES] = N_EDGES;
        }
        bar_n(1, NCSR);
        for (int e = gt; e < N_EDGES; e += gs) {
            int dn = load_idx(dstp, e, is64);
            int s  = load_idx(srcp, e, is64);
            int pos = atomicAdd(&g_cursor[dn], 1);
            g_csr[g_rs[dn] + pos] = s;
        }
    } else {
        // ================= proj0 role (overlapped) =================
        stage_W(W_self0, W_neigh0, tid);
        __syncthreads();
        dense_proj(x, g_h, 0, tid);
    }
    bar_n(0, GRID);

    // ---- agg0: g_h = relu(g_h + mean(P0) + b0) ----
    agg_combine<true>(g_h, b0, 1, tid);
    bar_n(0, GRID);

    // ---- proj1: outp = g_h@Ws1, g_ph = half(g_h@Wn1) ----
    stage_W(W_self1, W_neigh1, tid);
    __syncthreads();
    dense_proj(g_h, outp, 2, tid);
    bar_n(0, GRID);

    // ---- agg1: outp = outp + mean(P1) + b1 ----
    agg_combine<false>(outp, b1, 3, tid);

    bar_n(0, GRID);
    if (bid == 0 && tid == 0) g_tile[0] = 0;
}

// ---------------- launch: ONE kernel = ONE graph node ----------------
extern "C" void kernel_launch(void* const* d_in, const int* in_sizes, int n_in,
                              void* d_out, int out_size) {
    const float* x        = (const float*)d_in[0];
    const void*  src      = d_in[1];
    const void*  dst      = d_in[2];
    const float* W_self0  = (const float*)d_in[3];
    const float* W_neigh0 = (const float*)d_in[4];
    const float* b0       = (const float*)d_in[5];
    const float* W_self1  = (const float*)d_in[6];
    const float* W_neigh1 = (const float*)d_in[7];
    const float* b1       = (const float*)d_in[8];
    float* outp = (float*)d_out;

    sage_fused_kernel<<<GRID, TPB>>>(x, src, dst,
                                     W_self0, W_neigh0, b0,
                                     W_self1, W_neigh1, b1, outp);
}

// round 15
// speedup vs baseline: 1.0322x; 1.0322x over previous
#include <cuda_runtime.h>
#include <cuda_fp16.h>

#define N_NODES 50000
#define N_EDGES 800000
#define D 64
#define GRID 592                         // 148 SMs x 4 blocks/SM
#define TPB 256
#define NCSR 200                         // blocks 0..199: CSR build; rest: proj0 overlap
#define CH 250                           // 200*250 = 50000 exact
#define TILE 32
#define NT ((N_NODES + TILE - 1) / TILE) // 1563 proj tiles
#define NWT4 (N_NODES / 4)               // 12500 agg warp-tiles of 4 rows
#define A_ST 72                          // A smem stride (halves)
#define W_ST 136                         // W smem stride (halves)

typedef unsigned long long ull;
typedef unsigned int u32;

// ---------------- scratch (static device globals; no allocation) ----------------
__device__ int   g_degcnt[N_NODES];
__device__ int   g_cursor[N_NODES];
__device__ int   g_rs[N_NODES + 1];
__device__ int   g_csr[N_EDGES];
__device__ int   g_bsum[NCSR];
__device__ int   g_boff[NCSR];
__device__ int   g_tile[4];              // proj0, agg0, proj1, agg1
__device__ float g_h[N_NODES * D];       // S then hidden h
__device__ u32   g_ph[N_NODES * (D / 2)];// P as half2

// barrier state: monotonic (replay-safe). id 0: global; id 1: CSR partial
__device__ unsigned g_bc[2];
__device__ unsigned g_bg[2];

__device__ __forceinline__ void bar_n(int id, unsigned nblk) {
    __syncthreads();
    if (threadIdx.x == 0) {
        __threadfence();
        unsigned my = atomicAdd(&g_bc[id], 1u) + 1u;
        unsigned need = (my + nblk - 1u) / nblk;
        if ((my % nblk) == 0u) atomicAdd(&g_bg[id], 1u);
        while (*(volatile unsigned*)&g_bg[id] < need) {}
        __threadfence();
    }
    __syncthreads();
}

__device__ __forceinline__ int load_idx(const void* p, int e, bool is64) {
    return is64 ? (int)((const long long*)p)[e] : ((const int*)p)[e];
}

// ---------------- mma helpers ----------------
__device__ __forceinline__ void ldsm_x4(u32& r0, u32& r1, u32& r2, u32& r3, u32 addr) {
    asm volatile("ldmatrix.sync.aligned.m8n8.x4.shared.b16 {%0,%1,%2,%3}, [%4];"
                 : "=r"(r0), "=r"(r1), "=r"(r2), "=r"(r3) : "r"(addr));
}
__device__ __forceinline__ void ldsm_x2_t(u32& r0, u32& r1, u32 addr) {
    asm volatile("ldmatrix.sync.aligned.m8n8.x2.trans.shared.b16 {%0,%1}, [%2];"
                 : "=r"(r0), "=r"(r1) : "r"(addr));
}
__device__ __forceinline__ void mma16816(float* c, const u32* a, u32 b0, u32 b1) {
    asm volatile(
        "mma.sync.aligned.m16n8k16.row.col.f32.f16.f16.f32 "
        "{%0,%1,%2,%3}, {%4,%5,%6,%7}, {%8,%9}, {%0,%1,%2,%3};"
        : "+f"(c[0]), "+f"(c[1]), "+f"(c[2]), "+f"(c[3])
        : "r"(a[0]), "r"(a[1]), "r"(a[2]), "r"(a[3]), "r"(b0), "r"(b1));
}

// ---------------- shared memory ----------------
__shared__ __align__(16) __half Ah[TILE * A_ST];   // 4.6 KB
__shared__ __align__(16) __half Wh[D * W_ST];      // 17.4 KB  [k][n: Ws|Wn] fp16
__shared__ int sscan[TPB];

// ---------------- W staging (once per proj phase) ----------------
__device__ __forceinline__ void stage_W(const float* __restrict__ Ws,
                                        const float* __restrict__ Wn, int tid) {
    for (int idx = tid; idx < D * 128; idx += TPB) {
        int k = idx >> 7, n = idx & 127;
        float w = (n < D) ? Ws[k * D + n] : Wn[k * D + (n - D)];
        Wh[k * W_ST + n] = __float2half(w);
    }
}

// ---------------- dense projection via HMMA: S = inp@Ws (fp32), P = inp@Wn (fp16) ----------------
__device__ void dense_proj(const float* __restrict__ inp, float* __restrict__ outS,
                           int ctr, int tid) {
    const int lane = tid & 31;
    const int w = tid >> 5;
    const int mg = w & 1;                // 16-row group
    const int nq = w >> 1;               // 32-col group: 0,1 -> S ; 2,3 -> P
    const int gid = lane >> 2;
    const int tig = lane & 3;
    __shared__ int s_t;

    const u32 ah_base = (u32)__cvta_generic_to_shared(Ah);
    const u32 wh_base = (u32)__cvta_generic_to_shared(Wh);
    const u32 a_lane = ah_base + ((mg * 16 + (lane & 15)) * A_ST + (lane >> 4) * 8) * 2;
    const u32 b_lane = wh_base + ((lane & 15) * W_ST + nq * 32) * 2;

    for (;;) {
        __syncthreads();
        if (tid == 0) s_t = atomicAdd(&g_tile[ctr], 1);
        __syncthreads();
        const int t = s_t;
        if (t >= NT) break;
        const int row0 = t * TILE;

        // stage A tile (32 x 64 fp16)
        {
            int r = tid >> 3, c = (tid & 7) * 8;
            int gr = row0 + r;
            float4 v0 = make_float4(0.f, 0.f, 0.f, 0.f), v1 = v0;
            if (gr < N_NODES) {
                v0 = *(const float4*)(inp + (long long)gr * D + c);
                v1 = *(const float4*)(inp + (long long)gr * D + c + 4);
            }
            __half2 h0 = __float22half2_rn(make_float2(v0.x, v0.y));
            __half2 h1 = __float22half2_rn(make_float2(v0.z, v0.w));
            __half2 h2 = __float22half2_rn(make_float2(v1.x, v1.y));
            __half2 h3 = __float22half2_rn(make_float2(v1.z, v1.w));
            uint4 pk;
            pk.x = *(u32*)&h0; pk.y = *(u32*)&h1; pk.z = *(u32*)&h2; pk.w = *(u32*)&h3;
            *(uint4*)&Ah[r * A_ST + c] = pk;
        }
        __syncthreads();

        float acc[4][4];
#pragma unroll
        for (int i = 0; i < 4; i++)
#pragma unroll
            for (int j = 0; j < 4; j++) acc[i][j] = 0.f;

#pragma unroll
        for (int kb = 0; kb < 4; kb++) {
            u32 a0, a1, a2, a3;
            ldsm_x4(a0, a1, a2, a3, a_lane + kb * 32);
            u32 af[4] = {a0, a1, a2, a3};
#pragma unroll
            for (int nb = 0; nb < 4; nb++) {
                u32 b0, b1;
                ldsm_x2_t(b0, b1, b_lane + (kb * 16 * W_ST + nb * 8) * 2);
                mma16816(acc[nb], af, b0, b1);
            }
        }

        const int r0g = row0 + mg * 16 + gid;
        const int r1g = r0g + 8;
        if (nq < 2) {
#pragma unroll
            for (int nb = 0; nb < 4; nb++) {
                int col = nq * 32 + nb * 8 + tig * 2;
                if (r0g < N_NODES)
                    *(float2*)(outS + (long long)r0g * D + col) = make_float2(acc[nb][0], acc[nb][1]);
                if (r1g < N_NODES)
                    *(float2*)(outS + (long long)r1g * D + col) = make_float2(acc[nb][2], acc[nb][3]);
            }
        } else {
#pragma unroll
            for (int nb = 0; nb < 4; nb++) {
                int col = (nq - 2) * 32 + nb * 8 + tig * 2;
                if (r0g < N_NODES) {
                    __half2 h = __float22half2_rn(make_float2(acc[nb][0], acc[nb][1]));
                    g_ph[r0g * (D / 2) + (col >> 1)] = *(u32*)&h;
                }
                if (r1g < N_NODES) {
                    __half2 h = __float22half2_rn(make_float2(acc[nb][2], acc[nb][3]));
                    g_ph[r1g * (D / 2) + (col >> 1)] = *(u32*)&h;
                }
            }
        }
    }
}

// ---------------- aggregation (feature-double-buffered gather) ----------------
template <bool RELU>
__device__ void agg_combine(float* __restrict__ io, const float* __restrict__ bias,
                            int ctr, int tid) {
    const int lane = tid & 31;
    const int q = lane >> 3;
    const int lq = lane & 7;
    float4 bv0 = *(const float4*)(bias + 8 * lq);
    float4 bv1 = *(const float4*)(bias + 8 * lq + 4);

    for (;;) {
        int t = 0;
        if (lane == 0) t = atomicAdd(&g_tile[ctr], 1);
        t = __shfl_sync(0xffffffffu, t, 0);
        if (t >= NWT4) break;
        const int row0 = t * 4;

        int rsv = 0;
        if (lane < 5) rsv = g_rs[row0 + lane];
        const int beg = __shfl_sync(0xffffffffu, rsv, q);
        const int end = __shfl_sync(0xffffffffu, rsv, q + 1);
        const int gr = row0 + q;
        const float iv = 1.0f / fmaxf((float)(end - beg), 1.0f);

        float2 ac0 = make_float2(0.f, 0.f), ac1 = ac0, ac2 = ac0, ac3 = ac0;
#define ACC8(U)                                                                        \
        {                                                                              \
            float2 f;                                                                  \
            f = __half22float2(*(__half2*)&(U).x); ac0.x += f.x; ac0.y += f.y;         \
            f = __half22float2(*(__half2*)&(U).y); ac1.x += f.x; ac1.y += f.y;         \
            f = __half22float2(*(__half2*)&(U).z); ac2.x += f.x; ac2.y += f.y;         \
            f = __half22float2(*(__half2*)&(U).w); ac3.x += f.x; ac3.y += f.y;         \
        }
        const int n4 = (end - beg) >> 2;      // full 4-edge batches
        if (n4 > 0) {
            // prologue: issue batch 0's feature loads
            int s0 = g_csr[beg], s1 = g_csr[beg + 1], s2 = g_csr[beg + 2], s3 = g_csr[beg + 3];
            uint4 u0 = __ldg((const uint4*)(g_ph + s0 * (D / 2)) + lq);
            uint4 u1 = __ldg((const uint4*)(g_ph + s1 * (D / 2)) + lq);
            uint4 u2 = __ldg((const uint4*)(g_ph + s2 * (D / 2)) + lq);
            uint4 u3 = __ldg((const uint4*)(g_ph + s3 * (D / 2)) + lq);
            int e = beg + 4;
            for (int it = 1; it < n4; it++, e += 4) {
                // issue batch it's loads BEFORE accumulating batch it-1
                int t0 = g_csr[e],     t1 = g_csr[e + 1];
                int t2 = g_csr[e + 2], t3 = g_csr[e + 3];
                uint4 v0 = __ldg((const uint4*)(g_ph + t0 * (D / 2)) + lq);
                uint4 v1 = __ldg((const uint4*)(g_ph + t1 * (D / 2)) + lq);
                uint4 v2 = __ldg((const uint4*)(g_ph + t2 * (D / 2)) + lq);
                uint4 v3 = __ldg((const uint4*)(g_ph + t3 * (D / 2)) + lq);
                ACC8(u0) ACC8(u1) ACC8(u2) ACC8(u3)
                u0 = v0; u1 = v1; u2 = v2; u3 = v3;
            }
            ACC8(u0) ACC8(u1) ACC8(u2) ACC8(u3)
        }
        // remainder edges
        for (int e = beg + n4 * 4; e < end; e++) {
            int s0 = g_csr[e];
            uint4 u0 = __ldg((const uint4*)(g_ph + s0 * (D / 2)) + lq);
            ACC8(u0)
        }
#undef ACC8
        float4 s0v = *((const float4*)(io + (long long)gr * D + 8 * lq));
        float4 s1v = *((const float4*)(io + (long long)gr * D + 8 * lq + 4));
        float4 o0, o1;
        o0.x = s0v.x + ac0.x * iv + bv0.x;
        o0.y = s0v.y + ac0.y * iv + bv0.y;
        o0.z = s0v.z + ac1.x * iv + bv0.z;
        o0.w = s0v.w + ac1.y * iv + bv0.w;
        o1.x = s1v.x + ac2.x * iv + bv1.x;
        o1.y = s1v.y + ac2.y * iv + bv1.y;
        o1.z = s1v.z + ac3.x * iv + bv1.z;
        o1.w = s1v.w + ac3.y * iv + bv1.w;
        if (RELU) {
            o0.x = fmaxf(o0.x, 0.f); o0.y = fmaxf(o0.y, 0.f);
            o0.z = fmaxf(o0.z, 0.f); o0.w = fmaxf(o0.w, 0.f);
            o1.x = fmaxf(o1.x, 0.f); o1.y = fmaxf(o1.y, 0.f);
            o1.z = fmaxf(o1.z, 0.f); o1.w = fmaxf(o1.w, 0.f);
        }
        *((float4*)(io + (long long)gr * D + 8 * lq)) = o0;
        *((float4*)(io + (long long)gr * D + 8 * lq + 4)) = o1;
    }
}

// ---------------- fused persistent kernel ----------------
__global__ void __launch_bounds__(TPB, 4)
sage_fused_kernel(const float* __restrict__ x,
                  const void* __restrict__ srcp,
                  const void* __restrict__ dstp,
                  const float* __restrict__ W_self0, const float* __restrict__ W_neigh0,
                  const float* __restrict__ b0,
                  const float* __restrict__ W_self1, const float* __restrict__ W_neigh1,
                  const float* __restrict__ b1,
                  float* __restrict__ outp) {
    const int tid = threadIdx.x;
    const int bid = blockIdx.x;

    // ---- index dtype detection ----
    if (tid == 0) sscan[0] = 0;
    __syncthreads();
    {
        int any = 0;
        const int* si = (const int*)srcp;
        for (int i = tid; i < 2048; i += TPB) any |= si[2 * i + 1];
        if (any) atomicOr(&sscan[0], 1);
    }
    __syncthreads();
    const bool is64 = (sscan[0] == 0);

    if (bid < NCSR) {
        // ================= CSR-builder role =================
        const int gt = bid * TPB + tid;
        const int gs = NCSR * TPB;
        for (int j = gt; j < N_NODES; j += gs) { g_degcnt[j] = 0; g_cursor[j] = 0; }
        if (gt >= 1 && gt < 4) g_tile[gt] = 0;
        bar_n(1, NCSR);
        for (int e = gt; e < N_EDGES; e += gs)
            atomicAdd(&g_degcnt[load_idx(dstp, e, is64)], 1);
        bar_n(1, NCSR);
        {
            int n0 = bid * CH;
            int v = (tid < CH) ? g_degcnt[n0 + tid] : 0;
            sscan[tid] = v; __syncthreads();
            for (int off = TPB / 2; off > 0; off >>= 1) {
                if (tid < off) sscan[tid] += sscan[tid + off];
                __syncthreads();
            }
            if (tid == 0) g_bsum[bid] = sscan[0];
        }
        bar_n(1, NCSR);
        if (bid == 0) {
            int v = (tid < NCSR) ? g_bsum[tid] : 0;
            sscan[tid] = v; __syncthreads();
            for (int off = 1; off < TPB; off <<= 1) {
                int t2 = (tid >= off) ? sscan[tid - off] : 0;
                __syncthreads();
                sscan[tid] += t2;
                __syncthreads();
            }
            if (tid < NCSR) g_boff[tid] = sscan[tid] - v;
        }
        bar_n(1, NCSR);
        {
            int n0 = bid * CH;
            int v = (tid < CH) ? g_degcnt[n0 + tid] : 0;
            sscan[tid] = v; __syncthreads();
            for (int off = 1; off < TPB; off <<= 1) {
                int t2 = (tid >= off) ? sscan[tid - off] : 0;
                __syncthreads();
                sscan[tid] += t2;
                __syncthreads();
            }
            if (tid < CH) g_rs[n0 + tid] = g_boff[bid] + sscan[tid] - v;
            if (bid == 0 && tid == 0) g_rs[N_NODES] = N_EDGES;
        }
        bar_n(1, NCSR);
        for (int e = gt; e < N_EDGES; e += gs) {
            int dn = load_idx(dstp, e, is64);
            int s  = load_idx(srcp, e, is64);
            int pos = atomicAdd(&g_cursor[dn], 1);
            g_csr[g_rs[dn] + pos] = s;
        }
    } else {
        // ================= proj0 role (overlapped) =================
        stage_W(W_self0, W_neigh0, tid);
        __syncthreads();
        dense_proj(x, g_h, 0, tid);
    }
    bar_n(0, GRID);

    // ---- agg0: g_h = relu(g_h + mean(P0) + b0) ----
    agg_combine<true>(g_h, b0, 1, tid);
    bar_n(0, GRID);

    // ---- proj1: outp = g_h@Ws1, g_ph = half(g_h@Wn1) ----
    stage_W(W_self1, W_neigh1, tid);
    __syncthreads();
    dense_proj(g_h, outp, 2, tid);
    bar_n(0, GRID);

    // ---- agg1: outp = outp + mean(P1) + b1 ----
    agg_combine<false>(outp, b1, 3, tid);

    bar_n(0, GRID);
    if (bid == 0 && tid == 0) g_tile[0] = 0;
}

// ---------------- launch: ONE kernel = ONE graph node ----------------
extern "C" void kernel_launch(void* const* d_in, const int* in_sizes, int n_in,
                              void* d_out, int out_size) {
    const float* x        = (const float*)d_in[0];
    const void*  src      = d_in[1];
    const void*  dst      = d_in[2];
    const float* W_self0  = (const float*)d_in[3];
    const float* W_neigh0 = (const float*)d_in[4];
    const float* b0       = (const float*)d_in[5];
    const float* W_self1  = (const float*)d_in[6];
    const float* W_neigh1 = (const float*)d_in[7];
    const float* b1       = (const float*)d_in[8];
    float* outp = (float*)d_out;

    sage_fused_kernel<<<GRID, TPB>>>(x, src, dst,
                                     W_self0, W_neigh0, b0,
                                     W_self1, W_neigh1, b1, outp);
}

// round 16
// speedup vs baseline: 1.1196x; 1.0847x over previous
#include <cuda_runtime.h>
#include <cuda_fp16.h>

#define N_NODES 50000
#define N_EDGES 800000
#define D 64
#define GRID 592                         // 148 SMs x 4 blocks/SM
#define TPB 256
#define NCSR 200                         // blocks 0..199: CSR build; rest: proj0 overlap
#define CH 250                           // 200*250 = 50000 exact
#define TILE 32
#define NT ((N_NODES + TILE - 1) / TILE) // 1563 tiles
#define NWT4 (N_NODES / 4)               // 12500 agg warp-tiles of 4 rows
#define A_ST 72                          // A smem stride (halves)
#define W_ST 136                         // W smem stride (halves)

typedef unsigned long long ull;
typedef unsigned int u32;

// ---------------- scratch (static device globals; no allocation) ----------------
__device__ int   g_degcnt[N_NODES];
__device__ int   g_cursor[N_NODES];
__device__ int   g_rs[N_NODES + 1];
__device__ int   g_csr[N_EDGES];
__device__ int   g_bsum[NCSR];
__device__ int   g_boff[NCSR];
__device__ int   g_tile[4];              // proj0, fused(agg0+proj1), agg1
__device__ float g_h[N_NODES * D];       // S0 (self projection of layer 0)
__device__ u32   g_ph[N_NODES * (D / 2)];  // P0 as half2
__device__ u32   g_ph2[N_NODES * (D / 2)]; // P1 as half2

// barrier state: monotonic (replay-safe). id 0: global; id 1: CSR partial
__device__ unsigned g_bc[2];
__device__ unsigned g_bg[2];

__device__ __forceinline__ void bar_n(int id, unsigned nblk) {
    __syncthreads();
    if (threadIdx.x == 0) {
        __threadfence();
        unsigned my = atomicAdd(&g_bc[id], 1u) + 1u;
        unsigned need = (my + nblk - 1u) / nblk;
        if ((my % nblk) == 0u) atomicAdd(&g_bg[id], 1u);
        while (*(volatile unsigned*)&g_bg[id] < need) {}
        __threadfence();
    }
    __syncthreads();
}

__device__ __forceinline__ int load_idx(const void* p, int e, bool is64) {
    return is64 ? (int)((const long long*)p)[e] : ((const int*)p)[e];
}

// ---------------- mma helpers ----------------
__device__ __forceinline__ void ldsm_x4(u32& r0, u32& r1, u32& r2, u32& r3, u32 addr) {
    asm volatile("ldmatrix.sync.aligned.m8n8.x4.shared.b16 {%0,%1,%2,%3}, [%4];"
                 : "=r"(r0), "=r"(r1), "=r"(r2), "=r"(r3) : "r"(addr));
}
__device__ __forceinline__ void ldsm_x2_t(u32& r0, u32& r1, u32 addr) {
    asm volatile("ldmatrix.sync.aligned.m8n8.x2.trans.shared.b16 {%0,%1}, [%2];"
                 : "=r"(r0), "=r"(r1) : "r"(addr));
}
__device__ __forceinline__ void mma16816(float* c, const u32* a, u32 b0, u32 b1) {
    asm volatile(
        "mma.sync.aligned.m16n8k16.row.col.f32.f16.f16.f32 "
        "{%0,%1,%2,%3}, {%4,%5,%6,%7}, {%8,%9}, {%0,%1,%2,%3};"
        : "+f"(c[0]), "+f"(c[1]), "+f"(c[2]), "+f"(c[3])
        : "r"(a[0]), "r"(a[1]), "r"(a[2]), "r"(a[3]), "r"(b0), "r"(b1));
}

// ---------------- shared memory ----------------
__shared__ __align__(16) __half Ah[TILE * A_ST];   // 4.6 KB
__shared__ __align__(16) __half Wh[D * W_ST];      // 17.4 KB  [k][n: Ws|Wn] fp16
__shared__ int sscan[TPB];
__shared__ int rbs[TILE + 1];

// ---------------- W staging (once per phase) ----------------
__device__ __forceinline__ void stage_W(const float* __restrict__ Ws,
                                        const float* __restrict__ Wn, int tid) {
    for (int idx = tid; idx < D * 128; idx += TPB) {
        int k = idx >> 7, n = idx & 127;
        float w = (n < D) ? Ws[k * D + n] : Wn[k * D + (n - D)];
        Wh[k * W_ST + n] = __float2half(w);
    }
}

// ---------------- MMA compute + epilogue (A in Ah, W in Wh) ----------------
__device__ __forceinline__ void mma_tile(float* __restrict__ outS, u32* __restrict__ outP,
                                         int row0, int tid) {
    const int lane = tid & 31;
    const int w = tid >> 5;
    const int mg = w & 1;
    const int nq = w >> 1;
    const int gid = lane >> 2;
    const int tig = lane & 3;

    const u32 ah_base = (u32)__cvta_generic_to_shared(Ah);
    const u32 wh_base = (u32)__cvta_generic_to_shared(Wh);
    const u32 a_lane = ah_base + ((mg * 16 + (lane & 15)) * A_ST + (lane >> 4) * 8) * 2;
    const u32 b_lane = wh_base + ((lane & 15) * W_ST + nq * 32) * 2;

    float acc[4][4];
#pragma unroll
    for (int i = 0; i < 4; i++)
#pragma unroll
        for (int j = 0; j < 4; j++) acc[i][j] = 0.f;

#pragma unroll
    for (int kb = 0; kb < 4; kb++) {
        u32 a0, a1, a2, a3;
        ldsm_x4(a0, a1, a2, a3, a_lane + kb * 32);
        u32 af[4] = {a0, a1, a2, a3};
#pragma unroll
        for (int nb = 0; nb < 4; nb++) {
            u32 b0, b1;
            ldsm_x2_t(b0, b1, b_lane + (kb * 16 * W_ST + nb * 8) * 2);
            mma16816(acc[nb], af, b0, b1);
        }
    }

    const int r0g = row0 + mg * 16 + gid;
    const int r1g = r0g + 8;
    if (nq < 2) {
#pragma unroll
        for (int nb = 0; nb < 4; nb++) {
            int col = nq * 32 + nb * 8 + tig * 2;
            if (r0g < N_NODES)
                *(float2*)(outS + (long long)r0g * D + col) = make_float2(acc[nb][0], acc[nb][1]);
            if (r1g < N_NODES)
                *(float2*)(outS + (long long)r1g * D + col) = make_float2(acc[nb][2], acc[nb][3]);
        }
    } else {
#pragma unroll
        for (int nb = 0; nb < 4; nb++) {
            int col = (nq - 2) * 32 + nb * 8 + tig * 2;
            if (r0g < N_NODES) {
                __half2 h = __float22half2_rn(make_float2(acc[nb][0], acc[nb][1]));
                outP[r0g * (D / 2) + (col >> 1)] = *(u32*)&h;
            }
            if (r1g < N_NODES) {
                __half2 h = __float22half2_rn(make_float2(acc[nb][2], acc[nb][3]));
                outP[r1g * (D / 2) + (col >> 1)] = *(u32*)&h;
            }
        }
    }
}

// ---------------- proj0: S0 = x@Ws0 (fp32 g_h), P0 = x@Wn0 (fp16 g_ph) ----------------
__device__ void dense_proj0(const float* __restrict__ inp, int tid) {
    __shared__ int s_t;
    for (;;) {
        __syncthreads();
        if (tid == 0) s_t = atomicAdd(&g_tile[0], 1);
        __syncthreads();
        const int t = s_t;
        if (t >= NT) break;
        const int row0 = t * TILE;
        {
            int r = tid >> 3, c = (tid & 7) * 8;
            int gr = row0 + r;
            float4 v0 = make_float4(0.f, 0.f, 0.f, 0.f), v1 = v0;
            if (gr < N_NODES) {
                v0 = *(const float4*)(inp + (long long)gr * D + c);
                v1 = *(const float4*)(inp + (long long)gr * D + c + 4);
            }
            __half2 h0 = __float22half2_rn(make_float2(v0.x, v0.y));
            __half2 h1 = __float22half2_rn(make_float2(v0.z, v0.w));
            __half2 h2 = __float22half2_rn(make_float2(v1.x, v1.y));
            __half2 h3 = __float22half2_rn(make_float2(v1.z, v1.w));
            uint4 pk;
            pk.x = *(u32*)&h0; pk.y = *(u32*)&h1; pk.z = *(u32*)&h2; pk.w = *(u32*)&h3;
            *(uint4*)&Ah[r * A_ST + c] = pk;
        }
        __syncthreads();
        mma_tile(g_h, g_ph, row0, tid);
    }
}

// ---------------- fused agg0 + proj1 ----------------
// Per 32-row tile: quarter-warps compute h = relu(S0 + mean(P0[neigh]) + b0) -> fp16 Ah;
// then HMMA: S1 -> outp, P1 -> g_ph2.
__device__ void fused_agg_proj(const float* __restrict__ b0, float* __restrict__ outp,
                               int tid) {
    const int lane = tid & 31;
    const int w = tid >> 5;
    const int q = lane >> 3;
    const int lq = lane & 7;
    float4 bv0 = *(const float4*)(b0 + 8 * lq);
    float4 bv1 = *(const float4*)(b0 + 8 * lq + 4);
    __shared__ int s_t;

    for (;;) {
        __syncthreads();
        if (tid == 0) s_t = atomicAdd(&g_tile[1], 1);
        __syncthreads();
        const int t = s_t;
        if (t >= NT) break;
        const int row0 = t * TILE;
        if (tid < TILE + 1) {
            int rr = row0 + tid; if (rr > N_NODES) rr = N_NODES;
            rbs[tid] = g_rs[rr];
        }
        __syncthreads();

        // gather: warp w owns rows w*4..w*4+3; quarter q -> row w*4+q
        {
            const int r = w * 4 + q;
            const int gr = row0 + r;
            uint4 pk = make_uint4(0, 0, 0, 0);
            if (gr < N_NODES) {
                const int beg = rbs[r], end = rbs[r + 1];
                const float iv = 1.0f / fmaxf((float)(end - beg), 1.0f);
                float2 ac0 = make_float2(0.f, 0.f), ac1 = ac0, ac2 = ac0, ac3 = ac0;
#define ACC8(U)                                                                        \
                {                                                                      \
                    float2 f;                                                          \
                    f = __half22float2(*(__half2*)&(U).x); ac0.x += f.x; ac0.y += f.y; \
                    f = __half22float2(*(__half2*)&(U).y); ac1.x += f.x; ac1.y += f.y; \
                    f = __half22float2(*(__half2*)&(U).z); ac2.x += f.x; ac2.y += f.y; \
                    f = __half22float2(*(__half2*)&(U).w); ac3.x += f.x; ac3.y += f.y; \
                }
                int e = beg;
                for (; e + 3 < end; e += 4) {
                    int s0 = g_csr[e],     s1 = g_csr[e + 1];
                    int s2 = g_csr[e + 2], s3 = g_csr[e + 3];
                    uint4 u0 = __ldg((const uint4*)(g_ph + s0 * (D / 2)) + lq);
                    uint4 u1 = __ldg((const uint4*)(g_ph + s1 * (D / 2)) + lq);
                    uint4 u2 = __ldg((const uint4*)(g_ph + s2 * (D / 2)) + lq);
                    uint4 u3 = __ldg((const uint4*)(g_ph + s3 * (D / 2)) + lq);
                    ACC8(u0) ACC8(u1) ACC8(u2) ACC8(u3)
                }
                for (; e < end; e++) {
                    int s0 = g_csr[e];
                    uint4 u0 = __ldg((const uint4*)(g_ph + s0 * (D / 2)) + lq);
                    ACC8(u0)
                }
#undef ACC8
                float4 s0v = *((const float4*)(g_h + (long long)gr * D + 8 * lq));
                float4 s1v = *((const float4*)(g_h + (long long)gr * D + 8 * lq + 4));
                float o0 = fmaxf(s0v.x + ac0.x * iv + bv0.x, 0.f);
                float o1 = fmaxf(s0v.y + ac0.y * iv + bv0.y, 0.f);
                float o2 = fmaxf(s0v.z + ac1.x * iv + bv0.z, 0.f);
                float o3 = fmaxf(s0v.w + ac1.y * iv + bv0.w, 0.f);
                float o4 = fmaxf(s1v.x + ac2.x * iv + bv1.x, 0.f);
                float o5 = fmaxf(s1v.y + ac2.y * iv + bv1.y, 0.f);
                float o6 = fmaxf(s1v.z + ac3.x * iv + bv1.z, 0.f);
                float o7 = fmaxf(s1v.w + ac3.y * iv + bv1.w, 0.f);
                __half2 h0 = __float22half2_rn(make_float2(o0, o1));
                __half2 h1 = __float22half2_rn(make_float2(o2, o3));
                __half2 h2 = __float22half2_rn(make_float2(o4, o5));
                __half2 h3 = __float22half2_rn(make_float2(o6, o7));
                pk.x = *(u32*)&h0; pk.y = *(u32*)&h1; pk.z = *(u32*)&h2; pk.w = *(u32*)&h3;
            }
            *(uint4*)&Ah[r * A_ST + 8 * lq] = pk;
        }
        __syncthreads();
        mma_tile(outp, g_ph2, row0, tid);
    }
}

// ---------------- agg1: outp[r] = outp[r] + mean(P1[neigh]) + b1 ----------------
__device__ void agg_final(float* __restrict__ io, const float* __restrict__ bias, int tid) {
    const int lane = tid & 31;
    const int q = lane >> 3;
    const int lq = lane & 7;
    float4 bv0 = *(const float4*)(bias + 8 * lq);
    float4 bv1 = *(const float4*)(bias + 8 * lq + 4);

    for (;;) {
        int t = 0;
        if (lane == 0) t = atomicAdd(&g_tile[2], 1);
        t = __shfl_sync(0xffffffffu, t, 0);
        if (t >= NWT4) break;
        const int row0 = t * 4;

        int rsv = 0;
        if (lane < 5) rsv = g_rs[row0 + lane];
        const int beg = __shfl_sync(0xffffffffu, rsv, q);
        const int end = __shfl_sync(0xffffffffu, rsv, q + 1);
        const int gr = row0 + q;
        const float iv = 1.0f / fmaxf((float)(end - beg), 1.0f);

        float2 ac0 = make_float2(0.f, 0.f), ac1 = ac0, ac2 = ac0, ac3 = ac0;
#define ACC8(U)                                                                        \
        {                                                                              \
            float2 f;                                                                  \
            f = __half22float2(*(__half2*)&(U).x); ac0.x += f.x; ac0.y += f.y;         \
            f = __half22float2(*(__half2*)&(U).y); ac1.x += f.x; ac1.y += f.y;         \
            f = __half22float2(*(__half2*)&(U).z); ac2.x += f.x; ac2.y += f.y;         \
            f = __half22float2(*(__half2*)&(U).w); ac3.x += f.x; ac3.y += f.y;         \
        }
        int e = beg;
        for (; e + 3 < end; e += 4) {
            int s0 = g_csr[e],     s1 = g_csr[e + 1];
            int s2 = g_csr[e + 2], s3 = g_csr[e + 3];
            uint4 u0 = __ldg((const uint4*)(g_ph2 + s0 * (D / 2)) + lq);
            uint4 u1 = __ldg((const uint4*)(g_ph2 + s1 * (D / 2)) + lq);
            uint4 u2 = __ldg((const uint4*)(g_ph2 + s2 * (D / 2)) + lq);
            uint4 u3 = __ldg((const uint4*)(g_ph2 + s3 * (D / 2)) + lq);
            ACC8(u0) ACC8(u1) ACC8(u2) ACC8(u3)
        }
        for (; e < end; e++) {
            int s0 = g_csr[e];
            uint4 u0 = __ldg((const uint4*)(g_ph2 + s0 * (D / 2)) + lq);
            ACC8(u0)
        }
#undef ACC8
        float4 s0v = *((const float4*)(io + (long long)gr * D + 8 * lq));
        float4 s1v = *((const float4*)(io + (long long)gr * D + 8 * lq + 4));
        float4 o0, o1;
        o0.x = s0v.x + ac0.x * iv + bv0.x;
        o0.y = s0v.y + ac0.y * iv + bv0.y;
        o0.z = s0v.z + ac1.x * iv + bv0.z;
        o0.w = s0v.w + ac1.y * iv + bv0.w;
        o1.x = s1v.x + ac2.x * iv + bv1.x;
        o1.y = s1v.y + ac2.y * iv + bv1.y;
        o1.z = s1v.z + ac3.x * iv + bv1.z;
        o1.w = s1v.w + ac3.y * iv + bv1.w;
        *((float4*)(io + (long long)gr * D + 8 * lq)) = o0;
        *((float4*)(io + (long long)gr * D + 8 * lq + 4)) = o1;
    }
}

// ---------------- fused persistent kernel ----------------
__global__ void __launch_bounds__(TPB, 4)
sage_fused_kernel(const float* __restrict__ x,
                  const void* __restrict__ srcp,
                  const void* __restrict__ dstp,
                  const float* __restrict__ W_self0, const float* __restrict__ W_neigh0,
                  const float* __restrict__ b0,
                  const float* __restrict__ W_self1, const float* __restrict__ W_neigh1,
                  const float* __restrict__ b1,
                  float* __restrict__ outp) {
    const int tid = threadIdx.x;
    const int bid = blockIdx.x;

    // ---- index dtype detection ----
    if (tid == 0) sscan[0] = 0;
    __syncthreads();
    {
        int any = 0;
        const int* si = (const int*)srcp;
        for (int i = tid; i < 2048; i += TPB) any |= si[2 * i + 1];
        if (any) atomicOr(&sscan[0], 1);
    }
    __syncthreads();
    const bool is64 = (sscan[0] == 0);

    if (bid < NCSR) {
        // ================= CSR-builder role =================
        const int gt = bid * TPB + tid;
        const int gs = NCSR * TPB;
        for (int j = gt; j < N_NODES; j += gs) { g_degcnt[j] = 0; g_cursor[j] = 0; }
        if (gt >= 1 && gt < 4) g_tile[gt] = 0;
        bar_n(1, NCSR);
        for (int e = gt; e < N_EDGES; e += gs)
            atomicAdd(&g_degcnt[load_idx(dstp, e, is64)], 1);
        bar_n(1, NCSR);
        {
            int n0 = bid * CH;
            int v = (tid < CH) ? g_degcnt[n0 + tid] : 0;
            sscan[tid] = v; __syncthreads();
            for (int off = TPB / 2; off > 0; off >>= 1) {
                if (tid < off) sscan[tid] += sscan[tid + off];
                __syncthreads();
            }
            if (tid == 0) g_bsum[bid] = sscan[0];
        }
        bar_n(1, NCSR);
        if (bid == 0) {
            int v = (tid < NCSR) ? g_bsum[tid] : 0;
            sscan[tid] = v; __syncthreads();
            for (int off = 1; off < TPB; off <<= 1) {
                int t2 = (tid >= off) ? sscan[tid - off] : 0;
                __syncthreads();
                sscan[tid] += t2;
                __syncthreads();
            }
            if (tid < NCSR) g_boff[tid] = sscan[tid] - v;
        }
        bar_n(1, NCSR);
        {
            int n0 = bid * CH;
            int v = (tid < CH) ? g_degcnt[n0 + tid] : 0;
            sscan[tid] = v; __syncthreads();
            for (int off = 1; off < TPB; off <<= 1) {
                int t2 = (tid >= off) ? sscan[tid - off] : 0;
                __syncthreads();
                sscan[tid] += t2;
                __syncthreads();
            }
            if (tid < CH) g_rs[n0 + tid] = g_boff[bid] + sscan[tid] - v;
            if (bid == 0 && tid == 0) g_rs[N_NODES] = N_EDGES;
        }
        bar_n(1, NCSR);
        for (int e = gt; e < N_EDGES; e += gs) {
            int dn = load_idx(dstp, e, is64);
            int s  = load_idx(srcp, e, is64);
            int pos = atomicAdd(&g_cursor[dn], 1);
            g_csr[g_rs[dn] + pos] = s;
        }
    } else {
        // ================= proj0 role (overlapped) =================
        stage_W(W_self0, W_neigh0, tid);
        __syncthreads();
        dense_proj0(x, tid);
    }
    bar_n(0, GRID);

    // ---- fused agg0 + proj1 ----
    stage_W(W_self1, W_neigh1, tid);
    __syncthreads();
    fused_agg_proj(b0, outp, tid);
    bar_n(0, GRID);

    // ---- agg1: outp = outp + mean(P1) + b1 ----
    agg_final(outp, b1, tid);

    bar_n(0, GRID);
    if (bid == 0 && tid == 0) g_tile[0] = 0;
}

// ---------------- launch: ONE kernel = ONE graph node ----------------
extern "C" void kernel_launch(void* const* d_in, const int* in_sizes, int n_in,
                              void* d_out, int out_size) {
    const float* x        = (const float*)d_in[0];
    const void*  src      = d_in[1];
    const void*  dst      = d_in[2];
    const float* W_self0  = (const float*)d_in[3];
    const float* W_neigh0 = (const float*)d_in[4];
    const float* b0       = (const float*)d_in[5];
    const float* W_self1  = (const float*)d_in[6];
    const float* W_neigh1 = (const float*)d_in[7];
    const float* b1       = (const float*)d_in[8];
    float* outp = (float*)d_out;

    sage_fused_kernel<<<GRID, TPB>>>(x, src, dst,
                                     W_self0, W_neigh0, b0,
                                     W_self1, W_neigh1, b1, outp);
}

// round 17
// speedup vs baseline: 1.1225x; 1.0025x over previous
#include <cuda_runtime.h>
#include <cuda_fp16.h>

#define N_NODES 50000
#define N_EDGES 800000
#define D 64
#define GRID 592                         // 148 SMs x 4 blocks/SM
#define TPB 256
#define NCSR 200                         // blocks 0..199: CSR build; rest: proj0 overlap
#define CH 250                           // 200*250 = 50000 exact
#define TILE 32
#define NT ((N_NODES + TILE - 1) / TILE) // 1563 tiles
#define NWT4 (N_NODES / 4)               // 12500 agg warp-tiles of 4 rows
#define A_ST 72                          // A smem stride (halves)
#define W_ST 136                         // W smem stride (halves)

typedef unsigned long long ull;
typedef unsigned int u32;

// ---------------- scratch (static device globals; no allocation) ----------------
__device__ int   g_degcnt[N_NODES];
__device__ int   g_cursor[N_NODES];
__device__ int   g_rs[N_NODES + 1];
__device__ int   g_csr[N_EDGES];
__device__ int   g_bsum[NCSR];
__device__ int   g_boff[NCSR];
__device__ int   g_tile[4];              // 0: proj0, 1: fused, 2: agg1
__device__ float g_h[N_NODES * D];       // S0 (fp32)
__device__ u32   g_ph[N_NODES * (D / 2)];  // P0 as half2
__device__ u32   g_ph2[N_NODES * (D / 2)]; // P1 as half2

// barrier state: monotonic (replay-safe). id 0: global; id 1: CSR partial
__device__ unsigned g_bc[2];
__device__ unsigned g_bg[2];

__device__ __forceinline__ void bar_n(int id, unsigned nblk) {
    __syncthreads();
    if (threadIdx.x == 0) {
        __threadfence();
        unsigned my = atomicAdd(&g_bc[id], 1u) + 1u;
        unsigned need = (my + nblk - 1u) / nblk;
        if ((my % nblk) == 0u) atomicAdd(&g_bg[id], 1u);
        while (*(volatile unsigned*)&g_bg[id] < need) {}
        __threadfence();
    }
    __syncthreads();
}

__device__ __forceinline__ int load_idx(const void* p, int e, bool is64) {
    return is64 ? (int)((const long long*)p)[e] : ((const int*)p)[e];
}

// ---------------- mma helpers ----------------
__device__ __forceinline__ void ldsm_x4(u32& r0, u32& r1, u32& r2, u32& r3, u32 addr) {
    asm volatile("ldmatrix.sync.aligned.m8n8.x4.shared.b16 {%0,%1,%2,%3}, [%4];"
                 : "=r"(r0), "=r"(r1), "=r"(r2), "=r"(r3) : "r"(addr));
}
__device__ __forceinline__ void ldsm_x2_t(u32& r0, u32& r1, u32 addr) {
    asm volatile("ldmatrix.sync.aligned.m8n8.x2.trans.shared.b16 {%0,%1}, [%2];"
                 : "=r"(r0), "=r"(r1) : "r"(addr));
}
__device__ __forceinline__ void mma16816(float* c, const u32* a, u32 b0, u32 b1) {
    asm volatile(
        "mma.sync.aligned.m16n8k16.row.col.f32.f16.f16.f32 "
        "{%0,%1,%2,%3}, {%4,%5,%6,%7}, {%8,%9}, {%0,%1,%2,%3};"
        : "+f"(c[0]), "+f"(c[1]), "+f"(c[2]), "+f"(c[3])
        : "r"(a[0]), "r"(a[1]), "r"(a[2]), "r"(a[3]), "r"(b0), "r"(b1));
}

// ---------------- shared memory ----------------
__shared__ __align__(16) __half Ah[2][TILE * A_ST]; // 9.2 KB double-buffered A tile
__shared__ __align__(16) __half Wh[D * W_ST];       // 17.4 KB  [k][n: Ws|Wn] fp16
__shared__ int sscan[TPB];
__shared__ int s_tid2[2];                            // double-buffered dynamic tile id

// ---------------- W staging (once per phase) ----------------
__device__ __forceinline__ void stage_W(const float* __restrict__ Ws,
                                        const float* __restrict__ Wn, int tid) {
    for (int idx = tid; idx < D * 128; idx += TPB) {
        int k = idx >> 7, n = idx & 127;
        float w = (n < D) ? Ws[k * D + n] : Wn[k * D + (n - D)];
        Wh[k * W_ST + n] = __float2half(w);
    }
}

// ---------------- MMA compute + epilogue (A in AhBuf, W in Wh) ----------------
__device__ __forceinline__ void mma_tile(float* __restrict__ outS, u32* __restrict__ outP,
                                         int row0, int tid, const __half* AhBuf) {
    const int lane = tid & 31;
    const int w = tid >> 5;
    const int mg = w & 1;
    const int nq = w >> 1;
    const int gid = lane >> 2;
    const int tig = lane & 3;

    const u32 ah_base = (u32)__cvta_generic_to_shared(AhBuf);
    const u32 wh_base = (u32)__cvta_generic_to_shared(Wh);
    const u32 a_lane = ah_base + ((mg * 16 + (lane & 15)) * A_ST + (lane >> 4) * 8) * 2;
    const u32 b_lane = wh_base + ((lane & 15) * W_ST + nq * 32) * 2;

    float acc[4][4];
#pragma unroll
    for (int i = 0; i < 4; i++)
#pragma unroll
        for (int j = 0; j < 4; j++) acc[i][j] = 0.f;

#pragma unroll
    for (int kb = 0; kb < 4; kb++) {
        u32 a0, a1, a2, a3;
        ldsm_x4(a0, a1, a2, a3, a_lane + kb * 32);
        u32 af[4] = {a0, a1, a2, a3};
#pragma unroll
        for (int nb = 0; nb < 4; nb++) {
            u32 b0, b1;
            ldsm_x2_t(b0, b1, b_lane + (kb * 16 * W_ST + nb * 8) * 2);
            mma16816(acc[nb], af, b0, b1);
        }
    }

    const int r0g = row0 + mg * 16 + gid;
    const int r1g = r0g + 8;
    if (nq < 2) {
#pragma unroll
        for (int nb = 0; nb < 4; nb++) {
            int col = nq * 32 + nb * 8 + tig * 2;
            if (r0g < N_NODES)
                *(float2*)(outS + (long long)r0g * D + col) = make_float2(acc[nb][0], acc[nb][1]);
            if (r1g < N_NODES)
                *(float2*)(outS + (long long)r1g * D + col) = make_float2(acc[nb][2], acc[nb][3]);
        }
    } else {
#pragma unroll
        for (int nb = 0; nb < 4; nb++) {
            int col = (nq - 2) * 32 + nb * 8 + tig * 2;
            if (r0g < N_NODES) {
                __half2 h = __float22half2_rn(make_float2(acc[nb][0], acc[nb][1]));
                outP[r0g * (D / 2) + (col >> 1)] = *(u32*)&h;
            }
            if (r1g < N_NODES) {
                __half2 h = __float22half2_rn(make_float2(acc[nb][2], acc[nb][3]));
                outP[r1g * (D / 2) + (col >> 1)] = *(u32*)&h;
            }
        }
    }
}

// ---------------- proj0: S0 = x@Ws0 (fp32 g_h), P0 = x@Wn0 (fp16 g_ph) ----------------
// Single-barrier-per-tile pipelined loop with double-buffered Ah.
__device__ __forceinline__ void stage_x_tile(const float* __restrict__ inp, int row0,
                                             int tid, __half* AhBuf) {
    int r = tid >> 3, c = (tid & 7) * 8;
    int gr = row0 + r;
    float4 v0 = make_float4(0.f, 0.f, 0.f, 0.f), v1 = v0;
    if (gr < N_NODES) {
        v0 = *(const float4*)(inp + (long long)gr * D + c);
        v1 = *(const float4*)(inp + (long long)gr * D + c + 4);
    }
    __half2 h0 = __float22half2_rn(make_float2(v0.x, v0.y));
    __half2 h1 = __float22half2_rn(make_float2(v0.z, v0.w));
    __half2 h2 = __float22half2_rn(make_float2(v1.x, v1.y));
    __half2 h3 = __float22half2_rn(make_float2(v1.z, v1.w));
    uint4 pk;
    pk.x = *(u32*)&h0; pk.y = *(u32*)&h1; pk.z = *(u32*)&h2; pk.w = *(u32*)&h3;
    *(uint4*)&AhBuf[r * A_ST + c] = pk;
}

__device__ void dense_proj0(const float* __restrict__ inp, int tid) {
    int p = 0;
    if (tid == 0) s_tid2[0] = atomicAdd(&g_tile[0], 1);
    __syncthreads();
    int t = s_tid2[0];
    if (t >= NT) return;
    for (;;) {
        if (tid == 0) s_tid2[p ^ 1] = atomicAdd(&g_tile[0], 1);
        stage_x_tile(inp, t * TILE, tid, Ah[p]);
        __syncthreads();                       // Ah[p] complete; next id visible
        mma_tile(g_h, g_ph, t * TILE, tid, Ah[p]);
        int t2 = s_tid2[p ^ 1];
        if (t2 >= NT) break;
        t = t2; p ^= 1;
    }
}

// ---------------- fused agg0 + proj1 (pipelined) ----------------
// gather h = relu(S0 + mean(P0[neigh]) + b0) -> fp16 Ah[p]; one barrier; HMMA -> outp/g_ph2.
__device__ void fused_agg_proj(const float* __restrict__ b0, float* __restrict__ outp,
                               int tid) {
    const int lane = tid & 31;
    const int w = tid >> 5;
    const int q = lane >> 3;
    const int lq = lane & 7;
    float4 bv0 = *(const float4*)(b0 + 8 * lq);
    float4 bv1 = *(const float4*)(b0 + 8 * lq + 4);

    int p = 0;
    if (tid == 0) s_tid2[0] = atomicAdd(&g_tile[1], 1);
    __syncthreads();
    int t = s_tid2[0];
    if (t >= NT) return;

    for (;;) {
        if (tid == 0) s_tid2[p ^ 1] = atomicAdd(&g_tile[1], 1);
        const int row0 = t * TILE;
        // warp-local row bounds: warp w owns rows w*4..w*4+3
        {
            int rsv = 0;
            if (lane < 5) {
                int rr = row0 + w * 4 + lane;
                if (rr > N_NODES) rr = N_NODES;
                rsv = g_rs[rr];
            }
            const int beg = __shfl_sync(0xffffffffu, rsv, q);
            const int end = __shfl_sync(0xffffffffu, rsv, q + 1);
            const int r = w * 4 + q;
            const int gr = row0 + r;
            uint4 pk = make_uint4(0, 0, 0, 0);
            if (gr < N_NODES) {
                const float iv = 1.0f / fmaxf((float)(end - beg), 1.0f);
                float2 ac0 = make_float2(0.f, 0.f), ac1 = ac0, ac2 = ac0, ac3 = ac0;
#define ACC8(U)                                                                        \
                {                                                                      \
                    float2 f;                                                          \
                    f = __half22float2(*(__half2*)&(U).x); ac0.x += f.x; ac0.y += f.y; \
                    f = __half22float2(*(__half2*)&(U).y); ac1.x += f.x; ac1.y += f.y; \
                    f = __half22float2(*(__half2*)&(U).z); ac2.x += f.x; ac2.y += f.y; \
                    f = __half22float2(*(__half2*)&(U).w); ac3.x += f.x; ac3.y += f.y; \
                }
                int e = beg;
                for (; e + 3 < end; e += 4) {
                    int s0 = g_csr[e],     s1 = g_csr[e + 1];
                    int s2 = g_csr[e + 2], s3 = g_csr[e + 3];
                    uint4 u0 = __ldg((const uint4*)(g_ph + s0 * (D / 2)) + lq);
                    uint4 u1 = __ldg((const uint4*)(g_ph + s1 * (D / 2)) + lq);
                    uint4 u2 = __ldg((const uint4*)(g_ph + s2 * (D / 2)) + lq);
                    uint4 u3 = __ldg((const uint4*)(g_ph + s3 * (D / 2)) + lq);
                    ACC8(u0) ACC8(u1) ACC8(u2) ACC8(u3)
                }
                for (; e < end; e++) {
                    int s0 = g_csr[e];
                    uint4 u0 = __ldg((const uint4*)(g_ph + s0 * (D / 2)) + lq);
                    ACC8(u0)
                }
#undef ACC8
                float4 s0v = *((const float4*)(g_h + (long long)gr * D + 8 * lq));
                float4 s1v = *((const float4*)(g_h + (long long)gr * D + 8 * lq + 4));
                float o0 = fmaxf(s0v.x + ac0.x * iv + bv0.x, 0.f);
                float o1 = fmaxf(s0v.y + ac0.y * iv + bv0.y, 0.f);
                float o2 = fmaxf(s0v.z + ac1.x * iv + bv0.z, 0.f);
                float o3 = fmaxf(s0v.w + ac1.y * iv + bv0.w, 0.f);
                float o4 = fmaxf(s1v.x + ac2.x * iv + bv1.x, 0.f);
                float o5 = fmaxf(s1v.y + ac2.y * iv + bv1.y, 0.f);
                float o6 = fmaxf(s1v.z + ac3.x * iv + bv1.z, 0.f);
                float o7 = fmaxf(s1v.w + ac3.y * iv + bv1.w, 0.f);
                __half2 h0 = __float22half2_rn(make_float2(o0, o1));
                __half2 h1 = __float22half2_rn(make_float2(o2, o3));
                __half2 h2 = __float22half2_rn(make_float2(o4, o5));
                __half2 h3 = __float22half2_rn(make_float2(o6, o7));
                pk.x = *(u32*)&h0; pk.y = *(u32*)&h1; pk.z = *(u32*)&h2; pk.w = *(u32*)&h3;
            }
            *(uint4*)&Ah[p][r * A_ST + 8 * lq] = pk;
        }
        __syncthreads();                       // Ah[p] complete; next id visible
        mma_tile(outp, g_ph2, row0, tid, Ah[p]);
        int t2 = s_tid2[p ^ 1];
        if (t2 >= NT) break;
        t = t2; p ^= 1;
    }
}

// ---------------- agg1: outp[r] = outp[r] + mean(P1[neigh]) + b1 ----------------
__device__ void agg_final(float* __restrict__ io, const float* __restrict__ bias, int tid) {
    const int lane = tid & 31;
    const int q = lane >> 3;
    const int lq = lane & 7;
    float4 bv0 = *(const float4*)(bias + 8 * lq);
    float4 bv1 = *(const float4*)(bias + 8 * lq + 4);

    for (;;) {
        int t = 0;
        if (lane == 0) t = atomicAdd(&g_tile[2], 1);
        t = __shfl_sync(0xffffffffu, t, 0);
        if (t >= NWT4) break;
        const int row0 = t * 4;

        int rsv = 0;
        if (lane < 5) rsv = g_rs[row0 + lane];
        const int beg = __shfl_sync(0xffffffffu, rsv, q);
        const int end = __shfl_sync(0xffffffffu, rsv, q + 1);
        const int gr = row0 + q;
        const float iv = 1.0f / fmaxf((float)(end - beg), 1.0f);

        float2 ac0 = make_float2(0.f, 0.f), ac1 = ac0, ac2 = ac0, ac3 = ac0;
#define ACC8(U)                                                                        \
        {                                                                              \
            float2 f;                                                                  \
            f = __half22float2(*(__half2*)&(U).x); ac0.x += f.x; ac0.y += f.y;         \
            f = __half22float2(*(__half2*)&(U).y); ac1.x += f.x; ac1.y += f.y;         \
            f = __half22float2(*(__half2*)&(U).z); ac2.x += f.x; ac2.y += f.y;         \
            f = __half22float2(*(__half2*)&(U).w); ac3.x += f.x; ac3.y += f.y;         \
        }
        int e = beg;
        for (; e + 3 < end; e += 4) {
            int s0 = g_csr[e],     s1 = g_csr[e + 1];
            int s2 = g_csr[e + 2], s3 = g_csr[e + 3];
            uint4 u0 = __ldg((const uint4*)(g_ph2 + s0 * (D / 2)) + lq);
            uint4 u1 = __ldg((const uint4*)(g_ph2 + s1 * (D / 2)) + lq);
            uint4 u2 = __ldg((const uint4*)(g_ph2 + s2 * (D / 2)) + lq);
            uint4 u3 = __ldg((const uint4*)(g_ph2 + s3 * (D / 2)) + lq);
            ACC8(u0) ACC8(u1) ACC8(u2) ACC8(u3)
        }
        for (; e < end; e++) {
            int s0 = g_csr[e];
            uint4 u0 = __ldg((const uint4*)(g_ph2 + s0 * (D / 2)) + lq);
            ACC8(u0)
        }
#undef ACC8
        float4 s0v = *((const float4*)(io + (long long)gr * D + 8 * lq));
        float4 s1v = *((const float4*)(io + (long long)gr * D + 8 * lq + 4));
        float4 o0, o1;
        o0.x = s0v.x + ac0.x * iv + bv0.x;
        o0.y = s0v.y + ac0.y * iv + bv0.y;
        o0.z = s0v.z + ac1.x * iv + bv0.z;
        o0.w = s0v.w + ac1.y * iv + bv0.w;
        o1.x = s1v.x + ac2.x * iv + bv1.x;
        o1.y = s1v.y + ac2.y * iv + bv1.y;
        o1.z = s1v.z + ac3.x * iv + bv1.z;
        o1.w = s1v.w + ac3.y * iv + bv1.w;
        *((float4*)(io + (long long)gr * D + 8 * lq)) = o0;
        *((float4*)(io + (long long)gr * D + 8 * lq + 4)) = o1;
    }
}

// ---------------- fused persistent kernel ----------------
__global__ void __launch_bounds__(TPB, 4)
sage_fused_kernel(const float* __restrict__ x,
                  const void* __restrict__ srcp,
                  const void* __restrict__ dstp,
                  const float* __restrict__ W_self0, const float* __restrict__ W_neigh0,
                  const float* __restrict__ b0,
                  const float* __restrict__ W_self1, const float* __restrict__ W_neigh1,
                  const float* __restrict__ b1,
                  float* __restrict__ outp) {
    const int tid = threadIdx.x;
    const int bid = blockIdx.x;

    // ---- index dtype detection ----
    if (tid == 0) sscan[0] = 0;
    __syncthreads();
    {
        int any = 0;
        const int* si = (const int*)srcp;
        for (int i = tid; i < 2048; i += TPB) any |= si[2 * i + 1];
        if (any) atomicOr(&sscan[0], 1);
    }
    __syncthreads();
    const bool is64 = (sscan[0] == 0);

    if (bid < NCSR) {
        // ================= CSR-builder role =================
        const int gt = bid * TPB + tid;
        const int gs = NCSR * TPB;
        for (int j = gt; j < N_NODES; j += gs) { g_degcnt[j] = 0; g_cursor[j] = 0; }
        if (gt >= 1 && gt < 4) g_tile[gt] = 0;
        bar_n(1, NCSR);
        for (int e = gt; e < N_EDGES; e += gs)
            atomicAdd(&g_degcnt[load_idx(dstp, e, is64)], 1);
        bar_n(1, NCSR);
        {
            int n0 = bid * CH;
            int v = (tid < CH) ? g_degcnt[n0 + tid] : 0;
            sscan[tid] = v; __syncthreads();
            for (int off = TPB / 2; off > 0; off >>= 1) {
                if (tid < off) sscan[tid] += sscan[tid + off];
                __syncthreads();
            }
            if (tid == 0) g_bsum[bid] = sscan[0];
        }
        bar_n(1, NCSR);
        if (bid == 0) {
            int v = (tid < NCSR) ? g_bsum[tid] : 0;
            sscan[tid] = v; __syncthreads();
            for (int off = 1; off < TPB; off <<= 1) {
                int t2 = (tid >= off) ? sscan[tid - off] : 0;
                __syncthreads();
                sscan[tid] += t2;
                __syncthreads();
            }
            if (tid < NCSR) g_boff[tid] = sscan[tid] - v;
        }
        bar_n(1, NCSR);
        {
            int n0 = bid * CH;
            int v = (tid < CH) ? g_degcnt[n0 + tid] : 0;
            sscan[tid] = v; __syncthreads();
            for (int off = 1; off < TPB; off <<= 1) {
                int t2 = (tid >= off) ? sscan[tid - off] : 0;
                __syncthreads();
                sscan[tid] += t2;
                __syncthreads();
            }
            if (tid < CH) g_rs[n0 + tid] = g_boff[bid] + sscan[tid] - v;
            if (bid == 0 && tid == 0) g_rs[N_NODES] = N_EDGES;
        }
        bar_n(1, NCSR);
        for (int e = gt; e < N_EDGES; e += gs) {
            int dn = load_idx(dstp, e, is64);
            int s  = load_idx(srcp, e, is64);
            int pos = atomicAdd(&g_cursor[dn], 1);
            g_csr[g_rs[dn] + pos] = s;
        }
    } else {
        // ================= proj0 role (overlapped) =================
        stage_W(W_self0, W_neigh0, tid);
        __syncthreads();
        dense_proj0(x, tid);
    }
    bar_n(0, GRID);

    // ---- fused agg0 + proj1 ----
    stage_W(W_self1, W_neigh1, tid);
    __syncthreads();
    fused_agg_proj(b0, outp, tid);
    bar_n(0, GRID);

    // ---- agg1: outp = outp + mean(P1) + b1 ----
    agg_final(outp, b1, tid);

    bar_n(0, GRID);
    if (bid == 0 && tid == 0) g_tile[0] = 0;
}

// ---------------- launch: ONE kernel = ONE graph node ----------------
extern "C" void kernel_launch(void* const* d_in, const int* in_sizes, int n_in,
                              void* d_out, int out_size) {
    const float* x        = (const float*)d_in[0];
    const void*  src      = d_in[1];
    const void*  dst      = d_in[2];
    const float* W_self0  = (const float*)d_in[3];
    const float* W_neigh0 = (const float*)d_in[4];
    const float* b0       = (const float*)d_in[5];
    const float* W_self1  = (const float*)d_in[6];
    const float* W_neigh1 = (const float*)d_in[7];
    const float* b1       = (const float*)d_in[8];
    float* outp = (float*)d_out;

    sage_fused_kernel<<<GRID, TPB>>>(x, src, dst,
                                     W_self0, W_neigh0, b0,
                                     W_self1, W_neigh1, b1, outp);
}